// round 9
// baseline (speedup 1.0000x reference)
#include <cuda_runtime.h>
#include <cuda_fp16.h>
#include <cstdint>

#define NB 8
#define NC 64
#define NH 256
#define NW 512
#define NK 9
#define BHW (NB * NH * NW)          // 1,048,576
#define HW (NH * NW)                // 131,072

typedef unsigned long long ull;

// Scratch: P[k][b][y][x] = sum_c W[c,k] * F[b,c,y,x]   (fp16: 18.9 MB, L2-resident)
__device__ __half g_P[(size_t)NK * BHW];

// Packed f32x2 FMA (sm_100+): d = a*b + c on two lanes at once.
#define FMA_F32X2(d, a, b, c) \
    asm("fma.rn.f32x2 %0, %1, %2, %3;" : "=l"(d) : "l"(a), "l"(b), "l"(c))

__device__ __forceinline__ void cp16(uint32_t dst, const void* src) {
    asm volatile("cp.async.cg.shared.global [%0], [%1], 16;" :: "r"(dst), "l"(src));
}
__device__ __forceinline__ void cpcommit() {
    asm volatile("cp.async.commit_group;");
}
template <int N> __device__ __forceinline__ void cpwait() {
    asm volatile("cp.async.wait_group %0;" :: "n"(N));
}

// ---------------------------------------------------------------------------
// Pass 1: channel reduction, cp.async-pipelined.
// One block per (b,y) row. 64 channels in 8 chunks of 8; THREE-stage smem
// ring (16 KB/stage, 48 KB dynamic) -> 4 blocks/SM, 32 warps (full occ),
// in-flight = 4 blocks x 2 pending stages x 16 KB = 128 KB/SM.
// ONE __syncthreads per chunk: refill targets stage (c+2)%3, which every
// thread finished reading an iteration ago and has since crossed the barrier.
// ---------------------------------------------------------------------------
__global__ void __launch_bounds__(256) pass1_kernel(
    const float* __restrict__ feature,   // [B, C, H, W]
    const float* __restrict__ weight)    // [1, C, 3, 3] -> [C, 9]
{
    extern __shared__ float buf[];       // [3 stages][8 ch][512 x] = 49152 B
    __shared__ float4 sw4[NK][NC / 2];   // {w_c,w_c,w_c1,w_c1} per (k, pair)

    const int t = threadIdx.x;

    for (int i = t; i < NK * (NC / 2); i += 256) {
        int k  = i % NK;
        int cc = i / NK;
        float w0 = weight[(2 * cc + 0) * NK + k];
        float w1 = weight[(2 * cc + 1) * NK + k];
        sw4[k][cc] = make_float4(w0, w0, w1, w1);
    }

    const int yb = blockIdx.x;           // b*NH + y
    const float* frow = feature
        + (size_t)(yb / NH) * NC * NH * NW + (size_t)(yb % NH) * NW;

    const uint32_t sbase = (uint32_t)__cvta_generic_to_shared(buf);

    // Fill stage s with chunk (8 channels): 1024 x 16B, 4 copies per thread.
#define FILL(s, chunk)                                                        \
    do {                                                                      \
        const float* src0 = frow + (size_t)((chunk) * 8) * (NH * NW);         \
        _Pragma("unroll")                                                     \
        for (int i = 0; i < 4; ++i) {                                         \
            int idx = t + i * 256;       /* 0..1023 */                        \
            int cc  = idx >> 7;          /* channel within chunk */           \
            int q   = idx & 127;         /* 16B unit within row */            \
            cp16(sbase + (uint32_t)((s) * 16384 + cc * 2048 + q * 16),        \
                 src0 + (size_t)cc * (NH * NW) + q * 4);                      \
        }                                                                     \
        cpcommit();                                                           \
    } while (0)

    ull acc[NK];
#pragma unroll
    for (int k = 0; k < NK; ++k) acc[k] = 0ull;

    // Prologue: 2 stages in flight.
    FILL(0, 0);
    FILL(1, 1);

#pragma unroll
    for (int chunk = 0; chunk < 8; ++chunk) {
        if (chunk < 7) cpwait<1>();      // chunk's group complete, 1 pending
        else           cpwait<0>();
        __syncthreads();                 // cross-thread visibility of stage

        const float* st = buf + (chunk % 3) * 4096;
#pragma unroll
        for (int p = 0; p < 4; ++p) {    // channel pairs within chunk
            ull f0 = *(const ull*)(st + (2 * p + 0) * 512 + 2 * t);
            ull f1 = *(const ull*)(st + (2 * p + 1) * 512 + 2 * t);
            int cidx = chunk * 4 + p;    // global pair index 0..31
#pragma unroll
            for (int k = 0; k < NK; ++k) {
                ulonglong2 wp = *(const ulonglong2*)&sw4[k][cidx];
                FMA_F32X2(acc[k], f0, wp.x, acc[k]);
                FMA_F32X2(acc[k], f1, wp.y, acc[k]);
            }
        }
        if (chunk + 2 < 8) FILL((chunk + 2) % 3, chunk + 2);
    }
#undef FILL

    // Store: thread owns x = {2t, 2t+1}; one 4B half2 store per tap.
    size_t pbase = (size_t)yb * NW + 2 * t;
#pragma unroll
    for (int k = 0; k < NK; ++k) {
        float2 v = *(float2*)&acc[k];
        __half2 h = __floats2half2_rn(v.x, v.y);
        *(__half2*)(g_P + (size_t)k * BHW + pbase) = h;
    }
}

// ---------------------------------------------------------------------------
// Pass 2: tap gather + 2x2 upsample. One thread per (h,w) x 4 batches;
// grid.y=2 covers the 8 batches. All 36 fp16 gathers explicitly staged into
// registers (128-reg budget via launch_bounds(256,2)) for full MLP, then
// reduced. Output written evict-first to keep L2 for P.
// ---------------------------------------------------------------------------
__global__ void __launch_bounds__(256, 2) pass2_kernel(
    const int* __restrict__ gi,    // [H, W, 9]
    const int* __restrict__ gj,    // [H, W, 9]
    float* __restrict__ out)       // [B, 1, 2H, 2W]
{
    int g = blockIdx.x * 256 + threadIdx.x;      // [0, H*W)
    int h = g / NW;
    int w = g % NW;
    int ib = g * NK;
    int b0 = blockIdx.y * 4;                      // batch group: 0 or 4

    int ys[NK], xs[NK];
#pragma unroll
    for (int k = 0; k < NK; ++k) ys[k] = gi[ib + k];
#pragma unroll
    for (int k = 0; k < NK; ++k) xs[k] = gj[ib + k];

    // Stage all 36 gathers (independent loads -> deep MLP).
    unsigned short v[NK][4];
#pragma unroll
    for (int k = 0; k < NK; ++k) {
        const unsigned short* Pk = (const unsigned short*)g_P + (size_t)k * BHW
                                 + ((size_t)b0 * NH + ys[k]) * NW + xs[k];
#pragma unroll
        for (int j = 0; j < 4; ++j)
            v[k][j] = Pk[(size_t)j * HW];
    }

    float acc[4] = {0.f, 0.f, 0.f, 0.f};
#pragma unroll
    for (int k = 0; k < NK; ++k)
#pragma unroll
        for (int j = 0; j < 4; ++j)
            acc[j] += __half2float(__ushort_as_half(v[k][j]));

    // out viewed as float2: [B][2H][NW]; evict-first stores (no reuse).
    float2* o2 = (float2*)out;
#pragma unroll
    for (int j = 0; j < 4; ++j) {
        float2 val = make_float2(acc[j], acc[j]);
        size_t row0 = ((size_t)(b0 + j) * (2 * NH) + 2 * h) * NW + w;
        asm volatile("st.global.cs.v2.f32 [%0], {%1, %2};"
                     :: "l"(o2 + row0), "f"(val.x), "f"(val.y));
        asm volatile("st.global.cs.v2.f32 [%0], {%1, %2};"
                     :: "l"(o2 + row0 + NW), "f"(val.x), "f"(val.y));
    }
}

// ---------------------------------------------------------------------------
// Launch: graph-capturable, allocation-free.
// Inputs (metadata order): feature f32, weight f32, gi i32, gj i32.
// ---------------------------------------------------------------------------
extern "C" void kernel_launch(void* const* d_in, const int* in_sizes, int n_in,
                              void* d_out, int out_size)
{
    const float* feature = (const float*)d_in[0];
    const float* weight  = (const float*)d_in[1];
    const int*   gi      = (const int*)d_in[2];
    const int*   gj      = (const int*)d_in[3];
    float*       out     = (float*)d_out;

    // 48 KB dynamic smem opt-in (idempotent host call).
    static bool attr_set = false;
    if (!attr_set) {
        cudaFuncSetAttribute(pass1_kernel,
                             cudaFuncAttributeMaxDynamicSharedMemorySize, 49152);
        attr_set = true;
    }

    // Pass 1: one block per (b,y) row: 2048 blocks x 256 threads, 48KB smem
    pass1_kernel<<<NB * NH, 256, 49152>>>(feature, weight);
    // Pass 2: thread per (h,w) x 4 batches; grid (512, 2) x 256
    dim3 g2(NH * NW / 256, 2);
    pass2_kernel<<<g2, 256>>>(gi, gj, out);
}